// round 8
// baseline (speedup 1.0000x reference)
#include <cuda_runtime.h>
#include <cuda_fp16.h>

#define N_I 500000
#define N_H 200000
#define F_I 32
#define F_H 16
#define EF  8
#define E1  2000000
#define E2  2000000

// ---- pre kernel geometry (per-warp pipelined tiles) ----
#define BI 512                 // indivi blocks
#define BH 128                 // house blocks
#define WI (BI * 8)            // 4096 indivi warps
#define WH (BH * 8)            // 1024 house warps
#define TILE_NI 16             // indivi nodes per warp-tile
#define TILE_NH 32             // house nodes per warp-tile
#define NTI ((N_I + TILE_NI - 1) / TILE_NI)   // 31250
#define NTH ((N_H + TILE_NH - 1) / TILE_NH)   // 6250
#define SI 36                  // staged indivi row stride (floats, 16B-mult)
#define SH 20                  // staged house row stride
#define WBUF 640               // floats per warp buffer >= max(16*36, 32*20)

// Packed per-source-node record, 32 B (one L2 sector):
//  [0..3]=y as 8x fp16 pairs, [4]=z fp32, [5..7] pad
__device__ __align__(32) float g_rec_h[(size_t)N_H * 8];
__device__ __align__(32) float g_rec_i[(size_t)N_I * 8];

__device__ __forceinline__ float pack2h(float a, float b) {
    __half2 h = __floats2half2_rn(a, b);
    return __uint_as_float(*reinterpret_cast<unsigned*>(&h));
}
__device__ __forceinline__ unsigned smem_u32(const void* p) {
    return (unsigned)__cvta_generic_to_shared(p);
}
__device__ __forceinline__ void cp16(unsigned dst, const void* src) {
    asm volatile("cp.async.ca.shared.global [%0], [%1], 16;\n" :: "r"(dst), "l"(src));
}
__device__ __forceinline__ void cp_commit() {
    asm volatile("cp.async.commit_group;\n" ::: "memory");
}
__device__ __forceinline__ void cp_wait1() {
    asm volatile("cp.async.wait_group 1;\n" ::: "memory");
}
__device__ __forceinline__ void cp_wait0() {
    asm volatile("cp.async.wait_group 0;\n" ::: "memory");
}

// ==========================================================================
// Pre kernel: per-warp cp.async double-buffered pipeline, no block syncs
// in the steady state. blocks [0,BI): indivi; [BI, BI+BH): house.
// ==========================================================================
__global__ void __launch_bounds__(256)
pre_kernel(const float* __restrict__ x_indivi,
           const float* __restrict__ x_house,
           const float* __restrict__ W_edge_i,  // [F_I, EF]
           const float* __restrict__ b_edge_i,  // [F_I]
           const float* __restrict__ W_edge_h,  // [F_H, EF]
           const float* __restrict__ b_edge_h,  // [F_H]
           const float* __restrict__ W_root_h,  // [1, F_I]
           const float* __restrict__ W_root_i,  // [1, F_I]
           const float* __restrict__ bias_h,    // [1]
           const float* __restrict__ bias_i,    // [1]
           float* __restrict__ out)
{
    __shared__ float sbuf[8][2][WBUF];     // 40 KB, per-warp double buffers
    __shared__ float sW[F_I * EF];
    __shared__ float sb[F_I];
    __shared__ float sWr[F_I];
    __shared__ float sbias;

    int t    = threadIdx.x;
    int wid  = t >> 5;
    int lane = t & 31;

    if (blockIdx.x < BI) {
        // ================== indivi region ==================
        sW[t] = W_edge_i[t];
        if (t < F_I) {
            sb[t]  = b_edge_i[t];
            sWr[t] = W_root_h[t] + W_root_i[t];
        }
        if (t == 0) sbias = bias_h[0] + bias_i[0];
        __syncthreads();                   // weights ready; warps free-run now

        int gw = blockIdx.x * 8 + wid;     // global warp id in [0, WI)
        const float4* x4 = reinterpret_cast<const float4*>(x_indivi);
        const long gmax = (long)N_I * (F_I / 4);

        // issue tile -> buffer (4 cp16 per lane: 128 float4 per tile)
        auto issue = [&](int tile, int buf) {
            long base_f4 = (long)tile * TILE_NI * (F_I / 4);
            unsigned s32 = smem_u32(sbuf[wid][buf]);
#pragma unroll
            for (int i = 0; i < 4; i++) {
                int  loc  = lane + i * 32;
                long gidx = base_f4 + loc;
                if (gidx < gmax) {
                    int row = loc >> 3, col = loc & 7;
                    cp16(s32 + (row * SI + col * 4) * 4, x4 + gidx);
                }
            }
            cp_commit();
        };

        int node_local = lane & 15;
        int half = lane >> 4;
        int f0 = half * 16;
        float lbias = sbias;

        int tile = gw;
        if (tile < NTI) issue(tile, 0);
        int buf = 0;
        while (tile < NTI) {
            int next = tile + WI;
            if (next < NTI) { issue(next, buf ^ 1); cp_wait1(); }
            else            { cp_wait0(); }
            __syncwarp();

            const float* xr = sbuf[wid][buf] + node_local * SI + f0;
            float y[EF];
#pragma unroll
            for (int k = 0; k < EF; k++) y[k] = 0.f;
            float z = 0.f, root = 0.f;
#pragma unroll
            for (int j = 0; j < 16; j++) {
                float xf = xr[j];
                int f = f0 + j;
#pragma unroll
                for (int k = 0; k < EF; k++) y[k] = fmaf(xf, sW[f*EF + k], y[k]);
                z    = fmaf(xf, sb[f],  z);
                root = fmaf(xf, sWr[f], root);
            }
#pragma unroll
            for (int k = 0; k < EF; k++)
                y[k] += __shfl_down_sync(0xffffffffu, y[k], 16);
            z    += __shfl_down_sync(0xffffffffu, z, 16);
            root += __shfl_down_sync(0xffffffffu, root, 16);

            int n = tile * TILE_NI + node_local;
            if (half == 0 && n < N_I) {
                float4* ro = reinterpret_cast<float4*>(g_rec_i + (size_t)n * 8);
                ro[0] = make_float4(pack2h(y[0], y[1]), pack2h(y[2], y[3]),
                                    pack2h(y[4], y[5]), pack2h(y[6], y[7]));
                ro[1] = make_float4(z, 0.f, 0.f, 0.f);
                out[n] = root + lbias;
            }
            __syncwarp();                   // buffer reusable
            tile = next;
            buf ^= 1;
        }
    } else {
        // ================== house region ==================
        if (t < F_H * EF) sW[t] = W_edge_h[t];
        if (t < F_H)      sb[t] = b_edge_h[t];
        __syncthreads();

        int gw = (blockIdx.x - BI) * 8 + wid;   // [0, WH)
        const float4* x4 = reinterpret_cast<const float4*>(x_house);
        const long gmax = (long)N_H * (F_H / 4);

        auto issue = [&](int tile, int buf) {
            long base_f4 = (long)tile * TILE_NH * (F_H / 4);
            unsigned s32 = smem_u32(sbuf[wid][buf]);
#pragma unroll
            for (int i = 0; i < 4; i++) {
                int  loc  = lane + i * 32;
                long gidx = base_f4 + loc;
                if (gidx < gmax) {
                    int row = loc >> 2, col = loc & 3;
                    cp16(s32 + (row * SH + col * 4) * 4, x4 + gidx);
                }
            }
            cp_commit();
        };

        int tile = gw;
        if (tile < NTH) issue(tile, 0);
        int buf = 0;
        while (tile < NTH) {
            int next = tile + WH;
            if (next < NTH) { issue(next, buf ^ 1); cp_wait1(); }
            else            { cp_wait0(); }
            __syncwarp();

            int n = tile * TILE_NH + lane;
            if (n < N_H) {
                const float* xr = sbuf[wid][buf] + lane * SH;
                float y[EF];
#pragma unroll
                for (int k = 0; k < EF; k++) y[k] = 0.f;
                float z = 0.f;
#pragma unroll
                for (int f = 0; f < F_H; f++) {
                    float xf = xr[f];
#pragma unroll
                    for (int k = 0; k < EF; k++) y[k] = fmaf(xf, sW[f*EF + k], y[k]);
                    z = fmaf(xf, sb[f], z);
                }
                float4* ro = reinterpret_cast<float4*>(g_rec_h + (size_t)n * 8);
                ro[0] = make_float4(pack2h(y[0], y[1]), pack2h(y[2], y[3]),
                                    pack2h(y[4], y[5]), pack2h(y[6], y[7]));
                ro[1] = make_float4(z, 0.f, 0.f, 0.f);
            }
            __syncwarp();
            tile = next;
            buf ^= 1;
        }
    }
}

// ==========================================================================
// Edge kernel: both relations, 1 edge/thread (R3 exact form, known-fast).
// ==========================================================================
__device__ __forceinline__ void
edge_body(const float* __restrict__ ea, const int* __restrict__ src,
          const int* __restrict__ dst, const float* __restrict__ rec,
          float* __restrict__ out, int e)
{
    int s = __ldg(src + e);
    int d = __ldg(dst + e);

    const float4* ar = reinterpret_cast<const float4*>(ea + (size_t)e * EF);
    float4 a0 = __ldg(ar);
    float4 a1 = __ldg(ar + 1);

    float4 v = __ldg(reinterpret_cast<const float4*>(rec + (size_t)s * 8));
    float  z = __ldg(rec + (size_t)s * 8 + 4);     // same 32B sector

    float2 f01 = __half22float2(*reinterpret_cast<__half2*>(&v.x));
    float2 f23 = __half22float2(*reinterpret_cast<__half2*>(&v.y));
    float2 f45 = __half22float2(*reinterpret_cast<__half2*>(&v.z));
    float2 f67 = __half22float2(*reinterpret_cast<__half2*>(&v.w));

    float m = z;
    m = fmaf(a0.x, f01.x, m);
    m = fmaf(a0.y, f01.y, m);
    m = fmaf(a0.z, f23.x, m);
    m = fmaf(a0.w, f23.y, m);
    m = fmaf(a1.x, f45.x, m);
    m = fmaf(a1.y, f45.y, m);
    m = fmaf(a1.z, f67.x, m);
    m = fmaf(a1.w, f67.y, m);

    atomicAdd(out + d, m);
}

__global__ void __launch_bounds__(256)
edge_fused_kernel(const float* __restrict__ ea1,
                  const int*   __restrict__ src1,
                  const int*   __restrict__ dst1,
                  const float* __restrict__ ea2,
                  const int*   __restrict__ src2,
                  const int*   __restrict__ dst2,
                  float* __restrict__ out)
{
    int e = blockIdx.x * 256 + threadIdx.x;
    if (e < E1) {
        edge_body(ea1, src1, dst1, g_rec_h, out, e);
    } else {
        int e2 = e - E1;
        if (e2 < E2)
            edge_body(ea2, src2, dst2, g_rec_i, out, e2);
    }
}

// ==========================================================================
extern "C" void kernel_launch(void* const* d_in, const int* in_sizes, int n_in,
                              void* d_out, int out_size)
{
    const float* x_indivi      = (const float*)d_in[0];
    const float* x_house       = (const float*)d_in[1];
    const float* edge_attr_h2i = (const float*)d_in[2];
    const float* edge_attr_i2i = (const float*)d_in[3];
    const float* W_edge_h2i    = (const float*)d_in[4];
    const float* b_edge_h2i    = (const float*)d_in[5];
    const float* W_edge_i2i    = (const float*)d_in[6];
    const float* b_edge_i2i    = (const float*)d_in[7];
    const float* W_root_h2i    = (const float*)d_in[8];
    const float* bias_h2i      = (const float*)d_in[9];
    const float* W_root_i2i    = (const float*)d_in[10];
    const float* bias_i2i      = (const float*)d_in[11];
    const int*   src_h2i       = (const int*)d_in[12];
    const int*   dst_h2i       = (const int*)d_in[13];
    const int*   src_i2i       = (const int*)d_in[14];
    const int*   dst_i2i       = (const int*)d_in[15];
    float* out = (float*)d_out;

    pre_kernel<<<BI + BH, 256>>>(
        x_indivi, x_house, W_edge_i2i, b_edge_i2i, W_edge_h2i, b_edge_h2i,
        W_root_h2i, W_root_i2i, bias_h2i, bias_i2i, out);

    int total_edges = E1 + E2;
    edge_fused_kernel<<<(total_edges + 255) / 256, 256>>>(
        edge_attr_h2i, src_h2i, dst_h2i,
        edge_attr_i2i, src_i2i, dst_i2i, out);
}